// round 7
// baseline (speedup 1.0000x reference)
#include <cuda_runtime.h>
#include <cuda_fp16.h>
#include <math.h>

#define NN 100000
#define NE 3200000
#define CH0 50048              // chunk-0 rows (multiple of 64 and of 16)

// ---------------- scratch (device globals) ----------------
__device__ __align__(16) float g_q [2*NN*64];
__device__ __align__(16) uint4 g_kvh[2*NN*16];   // per node,lane: {k0..3,v0..3} fp16
__device__ __align__(16) float g_s [2*NN*64];
__device__ __align__(16) float g_h [NN*64];
__device__ __align__(16) float g_q3 [NN*4];
__device__ __align__(16) float g_s3 [NN*4];
__device__ __align__(32) float g_kv3[NN*8];
__device__ int g_deg[NN];
__device__ int g_ptr[NN+1];
__device__ int g_cur[NN];
__device__ int g_esrc[NE];

// ---------------- CSR build ----------------
__global__ void hist_k(const int* __restrict__ ei){
    int i = blockIdx.x*blockDim.x + threadIdx.x;
    if (i < NE/4){
        int4 d = ((const int4*)(ei + NE))[i];
        atomicAdd(&g_deg[d.x], 1);
        atomicAdd(&g_deg[d.y], 1);
        atomicAdd(&g_deg[d.z], 1);
        atomicAdd(&g_deg[d.w], 1);
    }
}
__global__ void __launch_bounds__(1024) scan_k(){
    __shared__ int sh[1024];
    int t = threadIdx.x;
    int carry = 0;
    for (int base = 0; base < NN; base += 4096){
        int v[4]; int s = 0;
        #pragma unroll
        for (int j = 0; j < 4; j++){
            int idx = base + t*4 + j;
            v[j] = (idx < NN) ? g_deg[idx] : 0;
            s += v[j];
        }
        sh[t] = s; __syncthreads();
        #pragma unroll
        for (int off = 1; off < 1024; off <<= 1){
            int x = (t >= off) ? sh[t-off] : 0;
            __syncthreads();
            sh[t] += x;
            __syncthreads();
        }
        int total = sh[1023];
        int excl = carry + sh[t] - s;
        #pragma unroll
        for (int j = 0; j < 4; j++){
            int idx = base + t*4 + j;
            if (idx < NN){ g_ptr[idx] = excl; g_cur[idx] = excl; }
            excl += v[j];
        }
        carry += total;
        __syncthreads();
    }
    if (t == 0) g_ptr[NN] = carry;
}
__global__ void scatter_k(const int* __restrict__ ei){
    int i = blockIdx.x*blockDim.x + threadIdx.x;
    if (i < NE/4){
        int4 s = ((const int4*)ei)[i];
        int4 d = ((const int4*)(ei + NE))[i];
        g_esrc[atomicAdd(&g_cur[d.x], 1)] = s.x;
        g_esrc[atomicAdd(&g_cur[d.y], 1)] = s.y;
        g_esrc[atomicAdd(&g_cur[d.z], 1)] = s.z;
        g_esrc[atomicAdd(&g_cur[d.w], 1)] = s.w;
    }
}

// ---------------- fused dual GEMM over row range ----------
__global__ void __launch_bounds__(128) gemm4(
    const float* __restrict__ X,
    const float* __restrict__ Wq, const float* __restrict__ bq,
    const float* __restrict__ Wk, const float* __restrict__ bk,
    const float* __restrict__ Wv, const float* __restrict__ bv,
    const float* __restrict__ Ws, const float* __restrict__ bs,
    int row0, int buf, int addres)
{
    __shared__ float Xs[64*64];
    __shared__ float Wsh[64*128];

    const float* WA; const float* WB; const float* bA; const float* bB;
    if (blockIdx.y == 0){ WA=Wq; bA=bq; WB=Wk; bB=bk; }
    else                { WA=Wv; bA=bv; WB=Ws; bB=bs; }

    int t  = threadIdx.x;
    int r0 = row0 + blockIdx.x*64;

    float* Q  = g_q + (size_t)buf*NN*64;
    float* S  = g_s + (size_t)buf*NN*64;
    uint4* KV = g_kvh + (size_t)buf*NN*16;

    int tx = t & 15, ty = t >> 4;
    int c  = tx*4;
    int ry = ty*8;

    // hoist bias loads into the prologue (overlaps with smem fill latency)
    float bA4[4], bB4[4];
    #pragma unroll
    for (int j = 0; j < 4; j++){ bA4[j] = bA[c+j]; bB4[j] = bB[c+j]; }

    #pragma unroll
    for (int i = 0; i < 16; i++){
        int idx = t + i*128;
        int k = idx >> 5, c4 = idx & 31;
        float4 w = (c4 < 16) ? ((const float4*)WA)[k*16 + c4]
                             : ((const float4*)WB)[k*16 + (c4-16)];
        ((float4*)Wsh)[k*32 + c4] = w;
    }
    #pragma unroll
    for (int i = 0; i < 8; i++){
        int idx = t + i*128;
        int row = idx >> 4, c4 = idx & 15;
        float4 xv = make_float4(0.f,0.f,0.f,0.f);
        if (r0 + row < NN) xv = ((const float4*)X)[(size_t)(r0+row)*16 + c4];
        int k0 = c4*4;
        Xs[(k0+0)*64 + (row ^ (((k0+0)&7)*8))] = xv.x;
        Xs[(k0+1)*64 + (row ^ (((k0+1)&7)*8))] = xv.y;
        Xs[(k0+2)*64 + (row ^ (((k0+2)&7)*8))] = xv.z;
        Xs[(k0+3)*64 + (row ^ (((k0+3)&7)*8))] = xv.w;
    }
    __syncthreads();

    unsigned long long acc[8][4];
    #pragma unroll
    for (int r = 0; r < 8; r++)
        #pragma unroll
        for (int q = 0; q < 4; q++) acc[r][q] = 0ull;

    #pragma unroll 8
    for (int k = 0; k < 64; k++){
        int sw = (k & 7)*8;
        const float* ap = &Xs[k*64 + (ry ^ sw)];
        float4 a0 = *(const float4*)ap;
        float4 a1 = *(const float4*)(ap + 4);
        ulonglong2 wA = *(const ulonglong2*)&Wsh[k*128 + c];
        ulonglong2 wB = *(const ulonglong2*)&Wsh[k*128 + 64 + c];
        float av[8] = {a0.x,a0.y,a0.z,a0.w,a1.x,a1.y,a1.z,a1.w};
        #pragma unroll
        for (int r = 0; r < 8; r++){
            unsigned long long ap2;
            asm("mov.b64 %0, {%1,%1};" : "=l"(ap2) : "f"(av[r]));
            asm("fma.rn.f32x2 %0, %1, %2, %0;" : "+l"(acc[r][0]) : "l"(ap2), "l"(wA.x));
            asm("fma.rn.f32x2 %0, %1, %2, %0;" : "+l"(acc[r][1]) : "l"(ap2), "l"(wA.y));
            asm("fma.rn.f32x2 %0, %1, %2, %0;" : "+l"(acc[r][2]) : "l"(ap2), "l"(wB.x));
            asm("fma.rn.f32x2 %0, %1, %2, %0;" : "+l"(acc[r][3]) : "l"(ap2), "l"(wB.y));
        }
    }

    bool res = (addres != 0) && (blockIdx.y == 1);   // residual -> s only

    #pragma unroll
    for (int r = 0; r < 8; r++){
        int row = ry + r;
        if (r0 + row >= NN) continue;
        float oA[4], oB[4];
        #pragma unroll
        for (int q = 0; q < 2; q++){
            float lo, hi;
            asm("mov.b64 {%0,%1}, %2;" : "=f"(lo), "=f"(hi) : "l"(acc[r][q]));
            oA[2*q] = lo + bA4[2*q]; oA[2*q+1] = hi + bA4[2*q+1];
            asm("mov.b64 {%0,%1}, %2;" : "=f"(lo), "=f"(hi) : "l"(acc[r][q+2]));
            oB[2*q] = lo + bB4[2*q]; oB[2*q+1] = hi + bB4[2*q+1];
        }
        if (res){
            #pragma unroll
            for (int j = 0; j < 4; j++){
                int cc = c + j;
                oB[j] += Xs[cc*64 + (row ^ ((cc & 7)*8))];
            }
        }
        size_t grow = (size_t)(r0+row);
        uint2* kvslot = (uint2*)&KV[grow*16 + tx];
        if (blockIdx.y == 0){
            ((float4*)Q)[grow*16 + tx] = make_float4(oA[0],oA[1],oA[2],oA[3]);
            __half2 h0 = __floats2half2_rn(oB[0], oB[1]);
            __half2 h1 = __floats2half2_rn(oB[2], oB[3]);
            uint2 u; *(__half2*)&u.x = h0; *(__half2*)&u.y = h1;
            kvslot[0] = u;
        } else {
            __half2 h0 = __floats2half2_rn(oA[0], oA[1]);
            __half2 h1 = __floats2half2_rn(oA[2], oA[3]);
            uint2 u; *(__half2*)&u.x = h0; *(__half2*)&u.y = h1;
            kvslot[1] = u;
            ((float4*)S)[grow*16 + tx] = make_float4(oB[0],oB[1],oB[2],oB[3]);
        }
    }
}

// ------- fused per-node attention, D=64, software-pipelined -------
__device__ __forceinline__ float dot4h(const float4& q, unsigned a, unsigned b){
    float2 f01 = __half22float2(*(__half2*)&a);
    float2 f23 = __half22float2(*(__half2*)&b);
    return q.x*f01.x + q.y*f01.y + q.z*f23.x + q.w*f23.y;
}
__device__ __forceinline__ void accv(float4& acc, float e, unsigned a, unsigned b){
    float2 f01 = __half22float2(*(__half2*)&a);
    float2 f23 = __half22float2(*(__half2*)&b);
    acc.x += e*f01.x; acc.y += e*f01.y; acc.z += e*f23.x; acc.w += e*f23.y;
}

__global__ void __launch_bounds__(256) edge64(int buf, int base, int nnodes){
    int lid = blockIdx.x*16 + (threadIdx.x >> 4);
    if (lid >= nnodes) return;
    int gid = base + lid;
    int lane = threadIdx.x & 15;
    unsigned gmask = 0xffffu << (threadIdx.x & 16);

    const float* Q  = g_q + (size_t)buf*NN*64;
    const float* S  = g_s + (size_t)buf*NN*64;
    const uint4* KV = g_kvh + (size_t)buf*NN*16;

    float4 q = ((const float4*)Q)[(size_t)gid*16 + lane];
    int beg = g_ptr[gid], end = g_ptr[gid+1];

    float4 acc = make_float4(0.f,0.f,0.f,0.f);
    float ssum = 0.f;

    int lim = beg + ((end - beg) & ~3);   // multiple-of-4 region
    int i = beg;
    if (i < lim){
        // prime group
        int s0 = g_esrc[i], s1 = g_esrc[i+1], s2 = g_esrc[i+2], s3 = g_esrc[i+3];
        uint4 kv0 = KV[(size_t)s0*16 + lane];
        uint4 kv1 = KV[(size_t)s1*16 + lane];
        uint4 kv2 = KV[(size_t)s2*16 + lane];
        uint4 kv3 = KV[(size_t)s3*16 + lane];
        for (i += 4; i < lim; i += 4){
            // issue next group's gathers BEFORE processing current group
            int t0 = g_esrc[i],   t1 = g_esrc[i+1];
            int t2 = g_esrc[i+2], t3 = g_esrc[i+3];
            uint4 n0 = KV[(size_t)t0*16 + lane];
            uint4 n1 = KV[(size_t)t1*16 + lane];
            uint4 n2 = KV[(size_t)t2*16 + lane];
            uint4 n3 = KV[(size_t)t3*16 + lane];
            // process current group (long shfl/exp chain hides n* latency)
            float d0 = dot4h(q, kv0.x, kv0.y);
            float d1 = dot4h(q, kv1.x, kv1.y);
            float d2 = dot4h(q, kv2.x, kv2.y);
            float d3 = dot4h(q, kv3.x, kv3.y);
            #pragma unroll
            for (int o = 8; o >= 1; o >>= 1){
                d0 += __shfl_xor_sync(gmask, d0, o);
                d1 += __shfl_xor_sync(gmask, d1, o);
                d2 += __shfl_xor_sync(gmask, d2, o);
                d3 += __shfl_xor_sync(gmask, d3, o);
            }
            float e0 = __expf(d0*0.125f);
            float e1 = __expf(d1*0.125f);
            float e2 = __expf(d2*0.125f);
            float e3 = __expf(d3*0.125f);
            ssum += (e0 + e1) + (e2 + e3);
            accv(acc, e0, kv0.z, kv0.w); accv(acc, e1, kv1.z, kv1.w);
            accv(acc, e2, kv2.z, kv2.w); accv(acc, e3, kv3.z, kv3.w);
            kv0 = n0; kv1 = n1; kv2 = n2; kv3 = n3;
        }
        // drain last primed group
        float d0 = dot4h(q, kv0.x, kv0.y);
        float d1 = dot4h(q, kv1.x, kv1.y);
        float d2 = dot4h(q, kv2.x, kv2.y);
        float d3 = dot4h(q, kv3.x, kv3.y);
        #pragma unroll
        for (int o = 8; o >= 1; o >>= 1){
            d0 += __shfl_xor_sync(gmask, d0, o);
            d1 += __shfl_xor_sync(gmask, d1, o);
            d2 += __shfl_xor_sync(gmask, d2, o);
            d3 += __shfl_xor_sync(gmask, d3, o);
        }
        float e0 = __expf(d0*0.125f);
        float e1 = __expf(d1*0.125f);
        float e2 = __expf(d2*0.125f);
        float e3 = __expf(d3*0.125f);
        ssum += (e0 + e1) + (e2 + e3);
        accv(acc, e0, kv0.z, kv0.w); accv(acc, e1, kv1.z, kv1.w);
        accv(acc, e2, kv2.z, kv2.w); accv(acc, e3, kv3.z, kv3.w);
    }
    for (; i < end; i++){
        int s0 = g_esrc[i];
        uint4 kv0 = KV[(size_t)s0*16 + lane];
        float d0 = dot4h(q, kv0.x, kv0.y);
        #pragma unroll
        for (int o = 8; o >= 1; o >>= 1)
            d0 += __shfl_xor_sync(gmask, d0, o);
        float e0 = __expf(d0*0.125f);
        ssum += e0;
        accv(acc, e0, kv0.z, kv0.w);
    }
    float inv = 1.0f / (ssum + 1e-16f);
    float4 sk = ((const float4*)S)[(size_t)gid*16 + lane];
    float4 o;
    o.x = tanhf(acc.x*inv + sk.x);
    o.y = tanhf(acc.y*inv + sk.y);
    o.z = tanhf(acc.z*inv + sk.z);
    o.w = tanhf(acc.w*inv + sk.w);
    ((float4*)g_h)[(size_t)gid*16 + lane] = o;
}

// ---------------- layer 3: 64 -> (3 x 4) GEMM over row range ----------------
__global__ void __launch_bounds__(256) gemm3(
    const float* __restrict__ X,
    const float* __restrict__ Wq, const float* __restrict__ bq,
    const float* __restrict__ Wk, const float* __restrict__ bk,
    const float* __restrict__ Wv, const float* __restrict__ bv,
    const float* __restrict__ Ws, const float* __restrict__ bs,
    const float* __restrict__ noise, int row0)
{
    __shared__ float w[64*12];
    __shared__ float bias[12];
    int t = threadIdx.x;
    if (t < 192){
        int kk = t/3, j = t%3;
        w[kk*12 + 0 + j] = Wq[t];
        w[kk*12 + 3 + j] = Wk[t];
        w[kk*12 + 6 + j] = Wv[t];
        w[kk*12 + 9 + j] = Ws[t];
    }
    if (t < 3){
        bias[t]   = bq[t];
        bias[3+t] = bk[t];
        bias[6+t] = bv[t];
        bias[9+t] = bs[t];
    }
    __syncthreads();
    int node = row0 + blockIdx.x*256 + t;
    if (node >= NN) return;
    float acc[12];
    #pragma unroll
    for (int j = 0; j < 12; j++) acc[j] = 0.f;
    #pragma unroll
    for (int kk = 0; kk < 16; kk++){
        float4 xv = ((const float4*)X)[(size_t)node*16 + kk];
        #pragma unroll
        for (int j = 0; j < 12; j++){
            acc[j] += xv.x * w[(kk*4+0)*12+j]
                    + xv.y * w[(kk*4+1)*12+j]
                    + xv.z * w[(kk*4+2)*12+j]
                    + xv.w * w[(kk*4+3)*12+j];
        }
    }
    float4 q3 = make_float4(acc[0]+bias[0], acc[1]+bias[1], acc[2]+bias[2], 0.f);
    float4 kva = make_float4(acc[3]+bias[3], acc[4]+bias[4], acc[5]+bias[5],
                             acc[6]+bias[6]);
    float4 kvb = make_float4(acc[7]+bias[7], acc[8]+bias[8], 0.f, 0.f);
    float4 s3 = make_float4(acc[9]+bias[9]   + 0.1f*noise[node*3+0],
                            acc[10]+bias[10] + 0.1f*noise[node*3+1],
                            acc[11]+bias[11] + 0.1f*noise[node*3+2], 0.f);
    ((float4*)g_q3)[node] = q3;
    ((float4*)g_kv3)[node*2]   = kva;
    ((float4*)g_kv3)[node*2+1] = kvb;
    ((float4*)g_s3)[node] = s3;
}

// ------- layer-3 per-node attention, software-pipelined -------
__global__ void __launch_bounds__(256) edge3(float* __restrict__ out){
    int node = blockIdx.x*256 + threadIdx.x;
    if (node >= NN) return;
    float4 q = ((const float4*)g_q3)[node];
    int beg = g_ptr[node], end = g_ptr[node+1];
    float sum = 0.f, ax = 0.f, ay = 0.f, az = 0.f;

    int lim = beg + ((end - beg) & ~1);
    int i = beg;
    if (i < lim){
        int s0 = g_esrc[i], s1 = g_esrc[i+1];
        float4 a0 = ((const float4*)g_kv3)[s0*2];
        float4 b0 = ((const float4*)g_kv3)[s0*2+1];
        float4 a1 = ((const float4*)g_kv3)[s1*2];
        float4 b1 = ((const float4*)g_kv3)[s1*2+1];
        for (i += 2; i < lim; i += 2){
            int t0 = g_esrc[i], t1 = g_esrc[i+1];
            float4 na0 = ((const float4*)g_kv3)[t0*2];
            float4 nb0 = ((const float4*)g_kv3)[t0*2+1];
            float4 na1 = ((const float4*)g_kv3)[t1*2];
            float4 nb1 = ((const float4*)g_kv3)[t1*2+1];
            float e0 = __expf((q.x*a0.x + q.y*a0.y + q.z*a0.z)*0.57735026919f);
            float e1 = __expf((q.x*a1.x + q.y*a1.y + q.z*a1.z)*0.57735026919f);
            sum += e0 + e1;
            ax += e0*a0.w + e1*a1.w;
            ay += e0*b0.x + e1*b1.x;
            az += e0*b0.y + e1*b1.y;
            a0 = na0; b0 = nb0; a1 = na1; b1 = nb1;
        }
        float e0 = __expf((q.x*a0.x + q.y*a0.y + q.z*a0.z)*0.57735026919f);
        float e1 = __expf((q.x*a1.x + q.y*a1.y + q.z*a1.z)*0.57735026919f);
        sum += e0 + e1;
        ax += e0*a0.w + e1*a1.w;
        ay += e0*b0.x + e1*b1.x;
        az += e0*b0.y + e1*b1.y;
    }
    if (i < end){
        int s0 = g_esrc[i];
        float4 a0 = ((const float4*)g_kv3)[s0*2];
        float4 b0 = ((const float4*)g_kv3)[s0*2+1];
        float e0 = __expf((q.x*a0.x + q.y*a0.y + q.z*a0.z)*0.57735026919f);
        sum += e0;
        ax += e0*a0.w; ay += e0*b0.x; az += e0*b0.y;
    }
    float inv = 1.0f / (sum + 1e-16f);
    float4 s3 = ((const float4*)g_s3)[node];
    out[node*3+0] = ax*inv + s3.x;
    out[node*3+1] = ay*inv + s3.y;
    out[node*3+2] = az*inv + s3.z;
}

// ---------------- launcher ----------------
extern "C" void kernel_launch(void* const* d_in, const int* in_sizes, int n_in,
                              void* d_out, int out_size)
{
    const float* x     = (const float*)d_in[0];
    const int*   ei    = (const int*)d_in[1];
    const float* noise = (const float*)d_in[2];
    const float* p[24];
    for (int i = 0; i < 24; i++) p[i] = (const float*)d_in[3+i];
    float* out = (float*)d_out;

    float* hptr = nullptr;
    cudaGetSymbolAddress((void**)&hptr, g_h);
    int* degptr = nullptr;
    cudaGetSymbolAddress((void**)&degptr, g_deg);

    static cudaStream_t s2 = nullptr;
    static cudaEvent_t ev_fork = nullptr, ev_csr = nullptr,
                       ev_e1a = nullptr, ev_g2a = nullptr,
                       ev_e2a = nullptr, ev_g3a = nullptr;
    if (!s2){
        cudaStreamCreateWithFlags(&s2, cudaStreamNonBlocking);
        cudaEventCreateWithFlags(&ev_fork, cudaEventDisableTiming);
        cudaEventCreateWithFlags(&ev_csr,  cudaEventDisableTiming);
        cudaEventCreateWithFlags(&ev_e1a,  cudaEventDisableTiming);
        cudaEventCreateWithFlags(&ev_g2a,  cudaEventDisableTiming);
        cudaEventCreateWithFlags(&ev_e2a,  cudaEventDisableTiming);
        cudaEventCreateWithFlags(&ev_g3a,  cudaEventDisableTiming);
    }

    int eb4 = (NE/4 + 255)/256;
    int nb  = (NN + 255)/256;
    const int CH1 = NN - CH0;
    dim3 gg_full((NN + 63)/64, 2);
    dim3 gg_a(CH0/64, 2);
    dim3 gg_b((CH1 + 63)/64, 2);
    int ng_a = CH0/16, ng_b = CH1/16;
    int nb3_a = (CH0 + 255)/256, nb3_b = (CH1 + 255)/256;

    // ---- CSR build on side stream, overlapped with layer-1 GEMM ----
    cudaEventRecord(ev_fork, 0);
    cudaStreamWaitEvent(s2, ev_fork, 0);
    cudaMemsetAsync(degptr, 0, NN*sizeof(int), s2);
    hist_k<<<eb4,256,0,s2>>>(ei);
    scan_k<<<1,1024,0,s2>>>();
    scatter_k<<<eb4,256,0,s2>>>(ei);
    cudaEventRecord(ev_csr, s2);

    gemm4<<<gg_full,128>>>(x, p[0],p[1],p[2],p[3],p[4],p[5],p[6],p[7], 0, 0, 0);

    cudaStreamWaitEvent(0, ev_csr, 0);
    edge64<<<ng_a,256>>>(0, 0, CH0);
    cudaEventRecord(ev_e1a, 0);
    edge64<<<ng_b,256>>>(0, CH0, CH1);

    cudaStreamWaitEvent(s2, ev_e1a, 0);
    gemm4<<<gg_a,128,0,s2>>>(hptr, p[8],p[9],p[10],p[11],p[12],p[13],p[14],p[15],
                             0, 1, 1);
    cudaEventRecord(ev_g2a, s2);

    gemm4<<<gg_b,128>>>(hptr, p[8],p[9],p[10],p[11],p[12],p[13],p[14],p[15],
                        CH0, 1, 1);
    cudaStreamWaitEvent(0, ev_g2a, 0);

    edge64<<<ng_a,256>>>(1, 0, CH0);
    cudaEventRecord(ev_e2a, 0);
    edge64<<<ng_b,256>>>(1, CH0, CH1);

    cudaStreamWaitEvent(s2, ev_e2a, 0);
    gemm3<<<nb3_a,256,0,s2>>>(hptr, p[16],p[17],p[18],p[19],p[20],p[21],p[22],p[23],
                              noise, 0);
    cudaEventRecord(ev_g3a, s2);

    gemm3<<<nb3_b,256>>>(hptr, p[16],p[17],p[18],p[19],p[20],p[21],p[22],p[23],
                         noise, CH0);
    cudaStreamWaitEvent(0, ev_g3a, 0);
    edge3<<<nb,256>>>(out);
}